// round 13
// baseline (speedup 1.0000x reference)
#include <cuda_runtime.h>
#include <cstdint>

// Shapes (fixed): B=8, L=256, F=512, U=512.
#define Bn 8
#define Ln 256
#define Fn 512
#define Un 512
#define Mn (Bn*Ln)   // 2048

// Scratch
__device__ __align__(16) float g_Q[Mn * Un];        // [2048][512]
__device__ __align__(16) float g_KT[Bn * Un * Ln];  // [8][512][256]  K+bh, u-major
__device__ __align__(16) float g_A[Bn * Ln * Ln];   // [8][256][256]  normalized weights

__device__ __forceinline__ float tanh_approx(float x) {
    float y;
    asm("tanh.approx.f32 %0, %1;" : "=f"(y) : "f"(x));
    return y;
}

__device__ __forceinline__ uint32_t cvt_tf32(float x) {
    uint32_t r;
    asm("cvt.rna.tf32.f32 %0, %1;" : "=r"(r) : "f"(x));
    return r;
}

#define MMA_TF32(c, A0, A1, A2, A3, B0, B1)                                   \
    asm volatile(                                                             \
        "mma.sync.aligned.m16n8k8.row.col.f32.tf32.tf32.f32 "                 \
        "{%0,%1,%2,%3}, {%4,%5,%6,%7}, {%8,%9}, {%0,%1,%2,%3};"               \
        : "+f"((c)[0]), "+f"((c)[1]), "+f"((c)[2]), "+f"((c)[3])              \
        : "r"(A0), "r"(A1), "r"(A2), "r"(A3), "r"(B0), "r"(B1))

// ---------------------------------------------------------------------------
// Kernel 1: tensor-core projections, smem-staged (validated, ~20us).
// ---------------------------------------------------------------------------
#define APITCH 20
#define BPITCH 136
#define A_FLOATS (2 * 128 * APITCH)
#define B_FLOATS (2 * 16 * BPITCH)

__global__ __launch_bounds__(256) void proj_tc_kernel(
    const float* __restrict__ X,    // [2048,512]
    const float* __restrict__ Wq,   // [512,512]
    const float* __restrict__ Wk,   // [512,512]
    const float* __restrict__ bh)   // [512]
{
    __shared__ __align__(16) float pool[A_FLOATS + B_FLOATS];
    typedef float ATile[128][APITCH];
    typedef float BTile[16][BPITCH];
    ATile* As = (ATile*)pool;
    BTile* Bs = (BTile*)(pool + A_FLOATS);
    typedef float KRow[65];
    KRow* kbuf = (KRow*)pool;   // epilogue alias

    const int bx  = blockIdx.x;
    const int isK = bx >> 6;
    const int m0  = ((bx >> 2) & 15) * 128;
    const int n0  = (bx & 3) * 128;
    const float* __restrict__ W = isK ? Wk : Wq;

    const int tid  = threadIdx.x;
    const int wid  = tid >> 5;
    const int lane = tid & 31;
    const int mw = wid >> 2;
    const int nw = wid & 3;
    const int gid = lane >> 2;
    const int tig = lane & 3;

    const int ma  = tid >> 2;
    const int k4a = (tid & 3) * 4;
    const int kb  = tid >> 5;
    const int n4b = (tid & 31) * 4;

    float acc[4][4][4];
#pragma unroll
    for (int i = 0; i < 4; i++)
#pragma unroll
        for (int j = 0; j < 4; j++)
#pragma unroll
            for (int r = 0; r < 4; r++) acc[i][j][r] = 0.f;

    float4 av0, av1, bv0, bv1;
#define PLOAD(K0)                                                             \
    do {                                                                      \
        av0 = *(const float4*)&X[(size_t)(m0 + ma) * Fn + (K0) + k4a];        \
        av1 = *(const float4*)&X[(size_t)(m0 + ma + 64) * Fn + (K0) + k4a];   \
        bv0 = *(const float4*)&W[(size_t)((K0) + kb) * Un + n0 + n4b];        \
        bv1 = *(const float4*)&W[(size_t)((K0) + kb + 8) * Un + n0 + n4b];    \
    } while (0)
#define PSTORE(S)                                                             \
    do {                                                                      \
        *(float4*)&As[S][ma][k4a]      = av0;                                 \
        *(float4*)&As[S][ma + 64][k4a] = av1;                                 \
        *(float4*)&Bs[S][kb][n4b]      = bv0;                                 \
        *(float4*)&Bs[S][kb + 8][n4b]  = bv1;                                 \
    } while (0)

    PLOAD(0);
    PSTORE(0);
    __syncthreads();

    for (int c = 0; c < 32; c++) {
        const int s = c & 1;
        if (c + 1 < 32) PLOAD((c + 1) * 16);
#pragma unroll
        for (int kk = 0; kk < 16; kk += 8) {
            uint32_t a[4][4], b[4][2];
#pragma unroll
            for (int mt = 0; mt < 4; mt++) {
                const int row = mw * 64 + mt * 16 + gid;
                a[mt][0] = cvt_tf32(As[s][row][kk + tig]);
                a[mt][1] = cvt_tf32(As[s][row + 8][kk + tig]);
                a[mt][2] = cvt_tf32(As[s][row][kk + tig + 4]);
                a[mt][3] = cvt_tf32(As[s][row + 8][kk + tig + 4]);
            }
#pragma unroll
            for (int nt = 0; nt < 4; nt++) {
                const int col = nw * 32 + nt * 8 + gid;
                b[nt][0] = cvt_tf32(Bs[s][kk + tig][col]);
                b[nt][1] = cvt_tf32(Bs[s][kk + tig + 4][col]);
            }
#pragma unroll
            for (int mt = 0; mt < 4; mt++)
#pragma unroll
                for (int nt = 0; nt < 4; nt++)
                    MMA_TF32(acc[mt][nt], a[mt][0], a[mt][1], a[mt][2],
                             a[mt][3], b[nt][0], b[nt][1]);
        }
        if (c + 1 < 32) {
            PSTORE((c + 1) & 1);
            __syncthreads();
        }
    }

    if (!isK) {
#pragma unroll
        for (int mt = 0; mt < 4; mt++) {
#pragma unroll
            for (int nt = 0; nt < 4; nt++) {
                const int row = m0 + mw * 64 + mt * 16 + gid;
                const int col = n0 + nw * 32 + nt * 8 + 2 * tig;
                float2 lo = make_float2(acc[mt][nt][0], acc[mt][nt][1]);
                float2 hi = make_float2(acc[mt][nt][2], acc[mt][nt][3]);
                *(float2*)&g_Q[(size_t)row * Un + col]       = lo;
                *(float2*)&g_Q[(size_t)(row + 8) * Un + col] = hi;
            }
        }
    } else {
        const int bidx = m0 >> 8;
        const int qi0  = m0 & 255;
#pragma unroll
        for (int pass = 0; pass < 2; pass++) {
            __syncthreads();
            if ((nw >> 1) == pass) {
#pragma unroll
                for (int mt = 0; mt < 4; mt++) {
#pragma unroll
                    for (int nt = 0; nt < 4; nt++) {
                        const int row = mw * 64 + mt * 16 + gid;
                        const int cl  = (nw & 1) * 32 + nt * 8 + 2 * tig;
                        kbuf[row][cl]         = acc[mt][nt][0];
                        kbuf[row][cl + 1]     = acc[mt][nt][1];
                        kbuf[row + 8][cl]     = acc[mt][nt][2];
                        kbuf[row + 8][cl + 1] = acc[mt][nt][3];
                    }
                }
            }
            __syncthreads();
#pragma unroll
            for (int i = tid; i < 64 * 128; i += 256) {
                const int ul = i >> 7;
                const int q  = i & 127;
                const int u  = n0 + pass * 64 + ul;
                g_KT[((size_t)bidx * Un + u) * Ln + qi0 + q] =
                    kbuf[q][ul] + __ldg(&bh[u]);
            }
        }
    }
#undef PLOAD
#undef PSTORE
}

// ---------------------------------------------------------------------------
// Kernel 2: score kernel — round-2's measured-optimal e-loop (512 CTAs x 512
// thr, qg=tid&63 fully-coalesced warp LDG, USPLIT=8 smem reduce), normalize,
// write g_A. No fused epilogue (X traffic moved to the cheap out_kernel).
// ---------------------------------------------------------------------------
#define PT 4
#define USPLIT 8
#define UCH (Un/USPLIT)   // 64

__global__ __launch_bounds__(512) void escore_kernel(
    const float* __restrict__ Wv)   // [512]
{
    __shared__ float4 QsT[Un];            // [u] -> Q[p0..p0+3][u]   8 KB
    __shared__ float  Wvs[Un];            // 2 KB
    __shared__ float  ep[USPLIT * PT * Ln];  // [us][p][q]          32 KB
    __shared__ float  aT[Ln * PT];        // [q][p]                  4 KB

    const int tid = threadIdx.x;
    const int b  = blockIdx.x >> 6;
    const int p0 = (blockIdx.x & 63) * PT;

    // Stage Q transposed and Wv
    {
        float* qst = (float*)QsT;
#pragma unroll
        for (int i = tid; i < PT * Un; i += 512) {
            int p = i >> 9;
            int u = i & 511;
            qst[u * 4 + p] = g_Q[((size_t)b * Ln + p0 + p) * Un + u];
        }
        Wvs[tid] = Wv[tid];
    }
    __syncthreads();

    const int us = tid >> 6;       // 0..7, warp-uniform
    const int qg = tid & 63;       // 4-wide q group; warp LDG = 512B contiguous
    const float4* __restrict__ kt4 = (const float4*)(g_KT + (size_t)b * Un * Ln);

    float4 e0 = make_float4(0.f,0.f,0.f,0.f), e1 = e0, e2 = e0, e3 = e0;
    const int u0 = us * UCH;
#pragma unroll 4
    for (int i = 0; i < UCH; i++) {
        const int u = u0 + i;
        float4 kv = __ldg(&kt4[u * 64 + qg]);
        float4 q4 = QsT[u];
        float  wv = Wvs[u];
        e0.x = fmaf(wv, tanh_approx(q4.x + kv.x), e0.x);
        e0.y = fmaf(wv, tanh_approx(q4.x + kv.y), e0.y);
        e0.z = fmaf(wv, tanh_approx(q4.x + kv.z), e0.z);
        e0.w = fmaf(wv, tanh_approx(q4.x + kv.w), e0.w);
        e1.x = fmaf(wv, tanh_approx(q4.y + kv.x), e1.x);
        e1.y = fmaf(wv, tanh_approx(q4.y + kv.y), e1.y);
        e1.z = fmaf(wv, tanh_approx(q4.y + kv.z), e1.z);
        e1.w = fmaf(wv, tanh_approx(q4.y + kv.w), e1.w);
        e2.x = fmaf(wv, tanh_approx(q4.z + kv.x), e2.x);
        e2.y = fmaf(wv, tanh_approx(q4.z + kv.y), e2.y);
        e2.z = fmaf(wv, tanh_approx(q4.z + kv.z), e2.z);
        e2.w = fmaf(wv, tanh_approx(q4.z + kv.w), e2.w);
        e3.x = fmaf(wv, tanh_approx(q4.w + kv.x), e3.x);
        e3.y = fmaf(wv, tanh_approx(q4.w + kv.y), e3.y);
        e3.z = fmaf(wv, tanh_approx(q4.w + kv.z), e3.z);
        e3.w = fmaf(wv, tanh_approx(q4.w + kv.w), e3.w);
    }
    // ba is a uniform shift of e -> cancels exactly in the exp-normalize.

    {
        float4* ep4 = (float4*)ep;
        ep4[(us * 4 + 0) * 64 + qg] = e0;
        ep4[(us * 4 + 1) * 64 + qg] = e1;
        ep4[(us * 4 + 2) * 64 + qg] = e2;
        ep4[(us * 4 + 3) * 64 + qg] = e3;
    }
    __syncthreads();

    // Reduce 8 u-split partials -> aT[q][p]
#pragma unroll
    for (int idx = tid; idx < PT * Ln; idx += 512) {
        int p = idx >> 8;
        int q = idx & 255;
        float s = 0.f;
#pragma unroll
        for (int u = 0; u < USPLIT; u++)
            s += ep[(u * 4 + p) * 256 + q];
        aT[q * 4 + p] = s;
    }
    __syncthreads();

    // Normalize rows in place: warp w handles row p = w (w < 4)
    {
        const int w = tid >> 5, l = tid & 31;
        if (w < PT) {
            float m = -1e30f;
#pragma unroll
            for (int j = 0; j < 8; j++) m = fmaxf(m, aT[(l + j * 32) * 4 + w]);
#pragma unroll
            for (int o = 16; o > 0; o >>= 1)
                m = fmaxf(m, __shfl_xor_sync(0xffffffffu, m, o));
            float ex[8];
            float s = 0.f;
#pragma unroll
            for (int j = 0; j < 8; j++) {
                ex[j] = __expf(aT[(l + j * 32) * 4 + w] - m);
                s += ex[j];
            }
#pragma unroll
            for (int o = 16; o > 0; o >>= 1)
                s += __shfl_xor_sync(0xffffffffu, s, o);
            float inv = 1.f / (s + 1e-7f);
#pragma unroll
            for (int j = 0; j < 8; j++) aT[(l + j * 32) * 4 + w] = ex[j] * inv;
        }
    }
    __syncthreads();

    // Store normalized weights: g_A[b][p0+p][q]  (coalesced over q)
#pragma unroll
    for (int idx = tid; idx < PT * Ln; idx += 512) {
        int p = idx >> 8;
        int q = idx & 255;
        g_A[((size_t)b * Ln + p0 + p) * Ln + q] = aT[q * 4 + p];
    }
}

// ---------------------------------------------------------------------------
// Kernel 3: epilogue GEMM out[p,f] = sum_q a[p][q] * X[b,q,f].
// 256 CTAs (64 p-tiles x 4 f-tiles), 256 threads; 32p x 128f tile, q=256.
// Total X traffic 32 MB (vs 256 MB if fused at PT=4).
// ---------------------------------------------------------------------------
#define OPT 32
#define OFT 128
#define APAD 36

__global__ __launch_bounds__(256) void out_kernel(
    const float* __restrict__ X,    // [8,256,512]
    float* __restrict__ out)        // [8,256,512]
{
    __shared__ float aT[Ln * APAD];   // [q][p_local], 36 KB

    const int tid = threadIdx.x;
    const int ftile = blockIdx.x & 3;
    const int ptile = blockIdx.x >> 2;   // 0..63
    const int b = ptile >> 3;
    const int prow0 = (ptile & 7) * OPT;
    const int f0 = ftile * OFT;

    // Load weights tile into smem (coalesced over q)
    {
        const float* asrc = g_A + ((size_t)b * Ln + prow0) * Ln;
#pragma unroll
        for (int idx = tid; idx < OPT * Ln; idx += 256) {
            int p = idx >> 8;
            int q = idx & 255;
            aT[q * APAD + p] = asrc[p * Ln + q];
        }
    }
    __syncthreads();

    // thread = (py 0..7 -> 4 p rows, lane 0..31 -> 4 f cols)
    const int py = tid >> 5;
    const int lane = tid & 31;
    const float4* __restrict__ xin4 =
        (const float4*)(X + (size_t)b * Ln * Fn) + ftile * 32 + lane;

    float4 o0 = make_float4(0.f,0.f,0.f,0.f), o1 = o0, o2 = o0, o3 = o0;
#pragma unroll 4
    for (int q = 0; q < Ln; q++) {
        float4 x4 = __ldg(&xin4[q * (Fn / 4)]);
        float4 a4 = *(const float4*)&aT[q * APAD + py * 4];  // warp-broadcast
        o0.x = fmaf(a4.x, x4.x, o0.x); o0.y = fmaf(a4.x, x4.y, o0.y);
        o0.z = fmaf(a4.x, x4.z, o0.z); o0.w = fmaf(a4.x, x4.w, o0.w);
        o1.x = fmaf(a4.y, x4.x, o1.x); o1.y = fmaf(a4.y, x4.y, o1.y);
        o1.z = fmaf(a4.y, x4.z, o1.z); o1.w = fmaf(a4.y, x4.w, o1.w);
        o2.x = fmaf(a4.z, x4.x, o2.x); o2.y = fmaf(a4.z, x4.y, o2.y);
        o2.z = fmaf(a4.z, x4.z, o2.z); o2.w = fmaf(a4.z, x4.w, o2.w);
        o3.x = fmaf(a4.w, x4.x, o3.x); o3.y = fmaf(a4.w, x4.y, o3.y);
        o3.z = fmaf(a4.w, x4.z, o3.z); o3.w = fmaf(a4.w, x4.w, o3.w);
    }

    float* obase = out + ((size_t)b * Ln + prow0 + py * 4) * Fn + f0 + lane * 4;
    *(float4*)&obase[0 * Fn] = o0;
    *(float4*)&obase[1 * Fn] = o1;
    *(float4*)&obase[2 * Fn] = o2;
    *(float4*)&obase[3 * Fn] = o3;
}

extern "C" void kernel_launch(void* const* d_in, const int* in_sizes, int n_in,
                              void* d_out, int out_size) {
    const float* X  = (const float*)d_in[0];
    const float* Wq = (const float*)d_in[1];
    const float* Wk = (const float*)d_in[2];
    const float* Wv = (const float*)d_in[3];
    const float* bh = (const float*)d_in[4];
    // d_in[5] = ba: cancels exactly in the exp-normalize; unused.
    float* out = (float*)d_out;

    proj_tc_kernel<<<128, 256>>>(X, Wq, Wk, bh);     // 128 CTAs

    escore_kernel<<<Bn * (Ln / PT), 512>>>(Wv);      // 512 CTAs x 512 thr

    out_kernel<<<(Mn / OPT) * (Fn / OFT), 256>>>(X, out);  // 256 CTAs
}